// round 14
// baseline (speedup 1.0000x reference)
#include <cuda_runtime.h>
#include <cuda_fp16.h>

// AntiAliasInterpolation2d: depthwise 13x13 Gaussian, stride 4, zero pad 6.
// Input [32,3,512,512] f32, weight [3,1,13,13] f32, output [32,3,128,128] f32.
//
// Separable (exact): 2D kernel = outer(g,g), g[j] = k2[6][j]/sqrt(k2[6][6]).
// R14: hpass loads at FLOAT2 granularity: 7 x LDG.64 per output (56B fetched
// vs 52B essential, 14 L1 wavefronts vs 32 with float4) -- removes the L1TEX
// wavefront bottleneck identified in R13 analysis. 2 rows/warp, all loads
// in flight before FMAs, __ldcs. vpass reverted to the R12 winner
// (thread = float4 x oy-pair, 768 CTAs).

#define IW   512
#define IW2  256                 // input row in float2
#define OW   128

__device__ __half g_tmp[96 * 512 * 128];   // 12.6 MB scratch

__device__ __forceinline__ float2 ldcs2(const float2* p) { return __ldcs(p); }

// K1: warp = TWO adjacent input rows; CTA = 16 rows; 3072 CTAs.
__global__ __launch_bounds__(256, 5)
void hpass_kernel(const float* __restrict__ inp, const float* __restrict__ w)
{
    const int tid  = threadIdx.x;
    const int lane = tid & 31;
    const int wid  = tid >> 5;

    const int wg = blockIdx.x * 8 + wid;      // global warp id
    const int r0 = 2 * wg;                    // rows r0, r0+1 (same image: 2|512)
    const int c  = (r0 >> 9) % 3;

    float g[7];
    {
        const float inv = 1.0f / sqrtf(w[c * 169 + 84]);
#pragma unroll
        for (int k = 0; k < 7; k++) g[k] = w[c * 169 + 78 + k] * inv;
    }

    const float2* ra = reinterpret_cast<const float2*>(inp) + (size_t)r0 * IW2;
    const float2* rb = ra + IW2;
    __half* da = g_tmp + (size_t)r0 * OW;

    const float2 z2 = make_float2(0.f, 0.f);

#pragma unroll
    for (int j = 0; j < 4; j++) {
        const int ox = lane + 32 * j;
        const int m  = 2 * ox;                // center float2 block

        // 14 independent LDG.64 (unit inter-lane stride -> 2 wavefronts each),
        // all issued before any FMA.
        float2 A[7], B[7];
#pragma unroll
        for (int q = 0; q < 7; q++) {
            const int b = m + q - 3;
            const bool ok = (b >= 0) && (b < IW2);
            A[q] = ok ? ldcs2(ra + b) : z2;
            B[q] = ok ? ldcs2(rb + b) : z2;
        }

        // block q holds taps 2q (x), 2q+1 (y); weights g[k<7?k:12-k]
        // x-chain: taps 0,2,4,6,8,10,12 -> g0,g2,g4,g6,g4,g2,g0
        // y-chain: taps 1,3,5,7,9,11    -> g1,g3,g5,g5,g3,g1
        float e0 =       g[0] * A[0].x;
        float e1 =       g[1] * A[0].y;
        e0 = fmaf(g[2], A[1].x, e0);
        e1 = fmaf(g[3], A[1].y, e1);
        e0 = fmaf(g[4], A[2].x, e0);
        e1 = fmaf(g[5], A[2].y, e1);
        e0 = fmaf(g[6], A[3].x, e0);
        e1 = fmaf(g[5], A[3].y, e1);
        e0 = fmaf(g[4], A[4].x, e0);
        e1 = fmaf(g[3], A[4].y, e1);
        e0 = fmaf(g[2], A[5].x, e0);
        e1 = fmaf(g[1], A[5].y, e1);
        e0 = fmaf(g[0], A[6].x, e0);

        float f0 =       g[0] * B[0].x;
        float f1 =       g[1] * B[0].y;
        f0 = fmaf(g[2], B[1].x, f0);
        f1 = fmaf(g[3], B[1].y, f1);
        f0 = fmaf(g[4], B[2].x, f0);
        f1 = fmaf(g[5], B[2].y, f1);
        f0 = fmaf(g[6], B[3].x, f0);
        f1 = fmaf(g[5], B[3].y, f1);
        f0 = fmaf(g[4], B[4].x, f0);
        f1 = fmaf(g[3], B[4].y, f1);
        f0 = fmaf(g[2], B[5].x, f0);
        f1 = fmaf(g[1], B[5].y, f1);
        f0 = fmaf(g[0], B[6].x, f0);

        da[ox]      = __float2half_rn(e0 + e1);
        da[OW + ox] = __float2half_rn(f0 + f1);
    }
}

// K2 (R12 winner): thread = one float4 column-group of an oy-PAIR.
// 96 images * 64 pairs * 32 col-groups = 196608 threads -> 768 CTAs.
__global__ __launch_bounds__(256, 6)
void vpass_kernel(const float* __restrict__ w, float* __restrict__ out)
{
    __shared__ float sw[8];
    const int tid = threadIdx.x;
    const int idx = blockIdx.x * 256 + tid;
    const int ox4 = idx & 31;                 // float4 column group
    const int t   = idx >> 5;                 // pair id: nc*64 + oyp
    const int oyp = t & 63;
    const int nc  = t >> 6;
    const int oy0 = 2 * oyp;

    const int c = ((blockIdx.x * 8) >> 6) % 3;   // 8 pairs/CTA, one image/CTA
    if (tid < 7)
        sw[tid] = w[c * 169 + 78 + tid] / sqrtf(w[c * 169 + 84]);
    __syncthreads();

    float g[7];
#pragma unroll
    for (int k = 0; k < 7; k++) g[k] = sw[k];

    const uint2* base = reinterpret_cast<const uint2*>(g_tmp + (size_t)nc * (IW * OW)) + ox4;
    const int ib = 4 * oy0 - 6;               // first row of out0's window

    float4 p0 = make_float4(0.f, 0.f, 0.f, 0.f);
    float4 p1 = make_float4(0.f, 0.f, 0.f, 0.f);
#pragma unroll
    for (int k = 0; k < 17; k++) {
        const int iy = ib + k;
        if (iy >= 0 && iy < IW) {
            uint2 raw = base[(size_t)iy * 32];
            float2 f01 = __half22float2(*reinterpret_cast<__half2*>(&raw.x));
            float2 f23 = __half22float2(*reinterpret_cast<__half2*>(&raw.y));
            if (k <= 12) {
                const float gk = g[k < 7 ? k : 12 - k];
                p0.x = fmaf(gk, f01.x, p0.x);
                p0.y = fmaf(gk, f01.y, p0.y);
                p0.z = fmaf(gk, f23.x, p0.z);
                p0.w = fmaf(gk, f23.y, p0.w);
            }
            if (k >= 4) {
                const int m = k - 4;
                const float gm = g[m < 7 ? m : 12 - m];
                p1.x = fmaf(gm, f01.x, p1.x);
                p1.y = fmaf(gm, f01.y, p1.y);
                p1.z = fmaf(gm, f23.x, p1.z);
                p1.w = fmaf(gm, f23.y, p1.w);
            }
        }
    }
    float4* ob = reinterpret_cast<float4*>(out) + ((size_t)nc * 128 + oy0) * 32 + ox4;
    ob[0]  = p0;
    ob[32] = p1;
}

extern "C" void kernel_launch(void* const* d_in, const int* in_sizes, int n_in,
                              void* d_out, int out_size)
{
    const float* inp = (const float*)d_in[0];   // [32,3,512,512]
    const float* wgt = (const float*)d_in[1];   // [3,1,13,13]
    float* out = (float*)d_out;                 // [32,3,128,128]

    hpass_kernel<<<96 * 512 / 16, 256>>>(inp, wgt);       // 3072 CTAs
    vpass_kernel<<<96 * 64 * 32 / 256, 256>>>(wgt, out);  // 768 CTAs
}

// round 15
// speedup vs baseline: 1.1317x; 1.1317x over previous
#include <cuda_runtime.h>
#include <cuda_fp16.h>

// AntiAliasInterpolation2d: depthwise 13x13 Gaussian, stride 4, zero pad 6.
// Input [32,3,512,512] f32, weight [3,1,13,13] f32, output [32,3,128,128] f32.
//
// Separable (exact): 2D kernel = outer(g,g), g[j] = k2[6][j]/sqrt(k2[6][6]).
// R15: hpass = R12 winner (2 rows/warp, 8 LDG.128 in flight, __ldcs), writing
// into a PADDED intermediate (6 zero rows above, 14 below each image; pads
// zeroed by spare hpass threads). vpass is then branch-free: 17 unconditional
// LDG.64 per thread (fully front-batched), no smem, no barriers, 128-thr CTAs.

#define IW    512
#define IW4   128                // input row in float4
#define OW    128
#define PROWS 532                // 6 pad + 512 + 14 pad rows per image

__device__ __half g_tmp[96 * PROWS * OW];   // 13.1 MB scratch

__device__ __forceinline__ float4 ldcs4(const float4* p) { return __ldcs(p); }

// K1: warp = TWO adjacent input rows; CTA = 16 rows; 3072 CTAs.
// Spare duty: first threads also zero the 20 pad rows of each image.
__global__ __launch_bounds__(256, 6)
void hpass_kernel(const float* __restrict__ inp, const float* __restrict__ w)
{
    const int tid  = threadIdx.x;
    const int lane = tid & 31;
    const int wid  = tid >> 5;

    // ---- pad zeroing: 96 images * 20 rows * 64 u32 = 122880 stores ----
    {
        const int gtid = blockIdx.x * 256 + tid;
        if (gtid < 96 * 20 * 64) {
            const int img  = gtid / (20 * 64);
            const int rem  = gtid - img * (20 * 64);
            const int prow = rem >> 6;            // 0..19
            const int col  = rem & 63;
            const int rr   = (prow < 6) ? prow : (512 + prow);  // 0..5, 518..531
            reinterpret_cast<unsigned*>(g_tmp)[((size_t)img * PROWS + rr) * 64 + col] = 0u;
        }
    }

    const int wg = blockIdx.x * 8 + wid;      // global warp id, 256 pairs/image
    const int nc = wg >> 8;
    const int pr = wg & 255;
    const int r0 = 2 * pr;                    // rows r0, r0+1 within image
    const int c  = nc % 3;

    float g[7];
    {
        const float inv = 1.0f / sqrtf(w[c * 169 + 84]);
#pragma unroll
        for (int k = 0; k < 7; k++) g[k] = w[c * 169 + 78 + k] * inv;
    }

    const float4* ra = reinterpret_cast<const float4*>(inp)
                     + ((size_t)nc * IW + r0) * IW4;
    const float4* rb = ra + IW4;
    __half* da = g_tmp + ((size_t)nc * PROWS + 6 + r0) * OW;

    const float4 z4 = make_float4(0.f, 0.f, 0.f, 0.f);

#pragma unroll
    for (int j = 0; j < 4; j++) {
        const int ox = lane + 32 * j;
        float4 a0 = (ox >= 2)       ? ldcs4(ra + ox - 2) : z4;
        float4 a1 = (ox >= 1)       ? ldcs4(ra + ox - 1) : z4;
        float4 a2 =                   ldcs4(ra + ox);
        float4 a3 = (ox <= IW4 - 2) ? ldcs4(ra + ox + 1) : z4;
        float4 b0 = (ox >= 2)       ? ldcs4(rb + ox - 2) : z4;
        float4 b1 = (ox >= 1)       ? ldcs4(rb + ox - 1) : z4;
        float4 b2 =                   ldcs4(rb + ox);
        float4 b3 = (ox <= IW4 - 2) ? ldcs4(rb + ox + 1) : z4;

        float e0 =       g[0] * a0.z;
        float e1 =       g[1] * a0.w;
        e0 = fmaf(g[2], a1.x, e0);
        e1 = fmaf(g[3], a1.y, e1);
        e0 = fmaf(g[4], a1.z, e0);
        e1 = fmaf(g[5], a1.w, e1);
        e0 = fmaf(g[6], a2.x, e0);
        e1 = fmaf(g[5], a2.y, e1);
        e0 = fmaf(g[4], a2.z, e0);
        e1 = fmaf(g[3], a2.w, e1);
        e0 = fmaf(g[2], a3.x, e0);
        e1 = fmaf(g[1], a3.y, e1);
        e0 = fmaf(g[0], a3.z, e0);

        float f0 =       g[0] * b0.z;
        float f1 =       g[1] * b0.w;
        f0 = fmaf(g[2], b1.x, f0);
        f1 = fmaf(g[3], b1.y, f1);
        f0 = fmaf(g[4], b1.z, f0);
        f1 = fmaf(g[5], b1.w, f1);
        f0 = fmaf(g[6], b2.x, f0);
        f1 = fmaf(g[5], b2.y, f1);
        f0 = fmaf(g[4], b2.z, f0);
        f1 = fmaf(g[3], b2.w, f1);
        f0 = fmaf(g[2], b3.x, f0);
        f1 = fmaf(g[1], b3.y, f1);
        f0 = fmaf(g[0], b3.z, f0);

        da[ox]      = __float2half_rn(e0 + e1);
        da[OW + ox] = __float2half_rn(f0 + f1);
    }
}

// K2: thread = one float4 column-group of an oy-PAIR; branch-free 17-tap loop.
// 196608 threads in 128-thread CTAs -> 1536 CTAs. No smem, no barriers.
__global__ __launch_bounds__(128, 12)
void vpass_kernel(const float* __restrict__ w, float* __restrict__ out)
{
    const int idx = blockIdx.x * 128 + threadIdx.x;
    const int ox4 = idx & 31;                 // float4 column group
    const int t   = idx >> 5;                 // warp-uniform: nc*64 + oyp
    const int oyp = t & 63;
    const int nc  = t >> 6;
    const int oy0 = 2 * oyp;
    const int c   = nc % 3;                   // warp-uniform

    float g[7];
    {
        const float inv = 1.0f / sqrtf(w[c * 169 + 84]);
#pragma unroll
        for (int k = 0; k < 7; k++) g[k] = w[c * 169 + 78 + k] * inv;
    }

    // padded rows: data row iy lives at padded row iy+6; iy may be -6..518
    const uint2* base = reinterpret_cast<const uint2*>(
                            g_tmp + ((size_t)nc * PROWS + 6) * OW) + ox4;
    const int ib = 8 * oyp - 6;               // first window row of out0

    float4 p0 = make_float4(0.f, 0.f, 0.f, 0.f);
    float4 p1 = make_float4(0.f, 0.f, 0.f, 0.f);
#pragma unroll
    for (int k = 0; k < 17; k++) {
        uint2 raw = base[(ptrdiff_t)(ib + k) * 32];
        float2 f01 = __half22float2(*reinterpret_cast<__half2*>(&raw.x));
        float2 f23 = __half22float2(*reinterpret_cast<__half2*>(&raw.y));
        if (k <= 12) {
            const float gk = g[k < 7 ? k : 12 - k];
            p0.x = fmaf(gk, f01.x, p0.x);
            p0.y = fmaf(gk, f01.y, p0.y);
            p0.z = fmaf(gk, f23.x, p0.z);
            p0.w = fmaf(gk, f23.y, p0.w);
        }
        if (k >= 4) {
            const int m = k - 4;
            const float gm = g[m < 7 ? m : 12 - m];
            p1.x = fmaf(gm, f01.x, p1.x);
            p1.y = fmaf(gm, f01.y, p1.y);
            p1.z = fmaf(gm, f23.x, p1.z);
            p1.w = fmaf(gm, f23.y, p1.w);
        }
    }
    float4* ob = reinterpret_cast<float4*>(out) + ((size_t)nc * 128 + oy0) * 32 + ox4;
    ob[0]  = p0;
    ob[32] = p1;
}

extern "C" void kernel_launch(void* const* d_in, const int* in_sizes, int n_in,
                              void* d_out, int out_size)
{
    const float* inp = (const float*)d_in[0];   // [32,3,512,512]
    const float* wgt = (const float*)d_in[1];   // [3,1,13,13]
    float* out = (float*)d_out;                 // [32,3,128,128]

    hpass_kernel<<<96 * 512 / 16, 256>>>(inp, wgt);       // 3072 CTAs
    vpass_kernel<<<96 * 64 * 32 / 128, 128>>>(wgt, out);  // 1536 CTAs
}